// round 8
// baseline (speedup 1.0000x reference)
#include <cuda_runtime.h>
#include <cuda_bf16.h>
#include <cstdint>
#include <cstddef>

// Problem constants
#define LSEQ 2048
#define EDIM 512
#define HEADS 8
#define DDIM 64
#define E3   1536
#define CHUNK 64
#define NCH  32

#define THETA_SCALE 7.66990393942820573e-4f  // (pi/2)/2048

// ---------------- scratch (device globals; no allocs allowed) ----------------
__device__ float g_qkv[LSEQ * E3];
__device__ float g_ckv[HEADS * NCH * 2 * DDIM * DDIM];
__device__ float g_ck [HEADS * NCH * 2 * DDIM];
__device__ float g_pkv[HEADS * NCH * 2 * DDIM * DDIM];
__device__ float g_pk [HEADS * NCH * 2 * DDIM];

// bf16 split buffers
__device__ __nv_bfloat16 g_xh[LSEQ * EDIM];
__device__ __nv_bfloat16 g_xl[LSEQ * EDIM];
__device__ __nv_bfloat16 g_wqh[E3 * EDIM];   // Wqkv^T  [1536][512]
__device__ __nv_bfloat16 g_wql[E3 * EDIM];
__device__ __nv_bfloat16 g_woh[EDIM * EDIM]; // Wout^T  [512][512]
__device__ __nv_bfloat16 g_wol[EDIM * EDIM];
__device__ __nv_bfloat16 g_ah[LSEQ * EDIM];  // attention out hi/lo
__device__ __nv_bfloat16 g_al[LSEQ * EDIM];

// ---------------- low-level helpers ----------------
__device__ __forceinline__ uint32_t smem_u32(const void* p) {
    uint32_t a;
    asm("{ .reg .u64 t; cvta.to.shared.u64 t, %1; cvt.u32.u64 %0, t; }"
        : "=r"(a) : "l"(p));
    return a;
}
#define CP_ASYNC16(dst, src) \
    asm volatile("cp.async.cg.shared.global [%0], [%1], 16;" :: "r"(dst), "l"(src))
#define CP_COMMIT() asm volatile("cp.async.commit_group;" ::: "memory")
#define CP_WAIT0()  asm volatile("cp.async.wait_group 0;" ::: "memory")
#define CP_WAIT1()  asm volatile("cp.async.wait_group 1;" ::: "memory")

__device__ __forceinline__ void ldmx4(uint32_t* r, uint32_t addr) {
    asm volatile("ldmatrix.sync.aligned.m8n8.x4.shared.b16 {%0,%1,%2,%3}, [%4];"
                 : "=r"(r[0]), "=r"(r[1]), "=r"(r[2]), "=r"(r[3]) : "r"(addr));
}
__device__ __forceinline__ void mma16816(float* c, const uint32_t* a, const uint32_t* b) {
    asm volatile(
        "mma.sync.aligned.m16n8k16.row.col.f32.bf16.bf16.f32 "
        "{%0,%1,%2,%3}, {%4,%5,%6,%7}, {%8,%9}, {%0,%1,%2,%3};"
        : "+f"(c[0]), "+f"(c[1]), "+f"(c[2]), "+f"(c[3])
        : "r"(a[0]), "r"(a[1]), "r"(a[2]), "r"(a[3]), "r"(b[0]), "r"(b[1]));
}

// ---------------- bf16 split conversion kernels ----------------
__global__ __launch_bounds__(256)
void split_bf16_kernel(const float* __restrict__ src,
                       __nv_bfloat16* __restrict__ hi, __nv_bfloat16* __restrict__ lo, int n) {
    int i = blockIdx.x * 256 + threadIdx.x;
    if (i < n) {
        float a = src[i];
        __nv_bfloat16 h = __float2bfloat16(a);
        hi[i] = h;
        lo[i] = __float2bfloat16(a - __bfloat162float(h));
    }
}

// W[K,N] -> WT hi/lo [N,K]  (tiled transpose)
__global__ __launch_bounds__(256)
void split_bf16_T_kernel(const float* __restrict__ W,
                         __nv_bfloat16* __restrict__ hiT, __nv_bfloat16* __restrict__ loT,
                         int K, int N) {
    __shared__ float t[32][33];
    const int tx = threadIdx.x & 31, ty = threadIdx.x >> 5;  // (32, 8)
    const int n0 = blockIdx.x * 32, k0 = blockIdx.y * 32;
    #pragma unroll
    for (int j = 0; j < 4; j++)
        t[ty + 8 * j][tx] = W[(size_t)(k0 + ty + 8 * j) * N + n0 + tx];
    __syncthreads();
    #pragma unroll
    for (int j = 0; j < 4; j++) {
        float a = t[tx][ty + 8 * j];  // = W[k0+tx][n0+ty+8j]
        __nv_bfloat16 h = __float2bfloat16(a);
        size_t o = (size_t)(n0 + ty + 8 * j) * K + k0 + tx;
        hiT[o] = h;
        loT[o] = __float2bfloat16(a - __bfloat162float(h));
    }
}

// ---------------- mma.sync bf16x3 GEMM: C[M,N] = A @ Bt^T + bias --------------
// 128 threads, 4 warps as 2(M) x 2(N). Warp tile (BM/2) x (BN/2).
// Fat warp tiles cut smem-crossbar bytes per HMMA (the measured bottleneck).
#define KC 32
#define AST 40   // smem row stride in bf16 elems

template<int BM, int BN>
__global__ __launch_bounds__(128, 2)
void mma_gemm_kernel(const __nv_bfloat16* __restrict__ Ah, const __nv_bfloat16* __restrict__ Al,
                     const __nv_bfloat16* __restrict__ Bh, const __nv_bfloat16* __restrict__ Bl,
                     const float* __restrict__ bias, float* __restrict__ C,
                     int N, int K) {
    constexpr int WM = BM / 2, WN = BN / 2;
    constexpr int MI = WM / 16;       // m16 fragments per warp
    constexpr int NJ = WN / 8;        // n8 fragments per warp
    constexpr int NL = NJ / 2;        // B ldmx4 per (hi|lo) per ks
    constexpr int TILE_A = BM * AST;
    constexpr int TILE_B = BN * AST;
    constexpr int BUF_E  = 2 * TILE_A + 2 * TILE_B;

    extern __shared__ __nv_bfloat16 smem[];
    const int tid = threadIdx.x;
    const int wid = tid >> 5, lane = tid & 31;
    const int bn0 = blockIdx.x * BN, bm0 = blockIdx.y * BM;
    const int wm = (wid & 1) * WM;
    const int wn = (wid >> 1) * WN;

    const uint32_t smb = smem_u32(smem);
    const int NCHK = K / KC;

    float acc[MI][NJ][4];
    #pragma unroll
    for (int mi = 0; mi < MI; mi++)
        #pragma unroll
        for (int nj = 0; nj < NJ; nj++)
            #pragma unroll
            for (int r = 0; r < 4; r++) acc[mi][nj][r] = 0.f;

    const __nv_bfloat16* srcs[4] = {Ah, Al, Bh, Bl};
    const int  srow[4] = {bm0, bm0, bn0, bn0};
    const int  titem[4] = {BM * KC / 8, BM * KC / 8, BN * KC / 8, BN * KC / 8};
    const uint32_t toff[4] = {0u, (uint32_t)TILE_A, (uint32_t)(2 * TILE_A),
                              (uint32_t)(2 * TILE_A + TILE_B)};

    auto load_chunk = [&](int b, int k0) {
        #pragma unroll
        for (int t = 0; t < 4; t++) {
            const __nv_bfloat16* s = srcs[t];
            uint32_t dbase = smb + (uint32_t)(b * BUF_E + toff[t]) * 2u;
            const int nit = titem[t];
            for (int item = tid; item < nit; item += 128) {
                int row = item >> 2, sub = item & 3;
                uint32_t d = dbase + (uint32_t)(row * AST + sub * 8) * 2u;
                const void* g = (const void*)(s + (size_t)(srow[t] + row) * K + k0 + sub * 8);
                CP_ASYNC16(d, g);
            }
        }
        CP_COMMIT();
    };

    load_chunk(0, 0);

    for (int c = 0; c < NCHK; c++) {
        const int b = c & 1;
        if (c + 1 < NCHK) {
            load_chunk(b ^ 1, (c + 1) * KC);
            CP_WAIT1();
        } else {
            CP_WAIT0();
        }
        __syncthreads();

        const uint32_t aBh = smb + (uint32_t)(b * BUF_E) * 2u;
        const uint32_t aBl = aBh + (uint32_t)TILE_A * 2u;
        const uint32_t bBh = aBh + (uint32_t)(2 * TILE_A) * 2u;
        const uint32_t bBl = bBh + (uint32_t)TILE_B * 2u;

        #pragma unroll
        for (int ks = 0; ks < KC; ks += 16) {
            const int arow = wm + (lane & 15);
            const int acol = ks + ((lane >> 4) << 3);
            uint32_t ah[MI][4], al[MI][4];
            #pragma unroll
            for (int mi = 0; mi < MI; mi++) {
                uint32_t off = (uint32_t)((arow + mi * 16) * AST + acol) * 2u;
                ldmx4(ah[mi], aBh + off);
                ldmx4(al[mi], aBl + off);
            }
            const int brow = wn + (lane & 7) + ((lane & 16) ? 8 : 0);
            const int bcol = ks + ((lane & 8) ? 8 : 0);
            uint32_t bh[NL][4], bl[NL][4];
            #pragma unroll
            for (int ni = 0; ni < NL; ni++) {
                uint32_t off = (uint32_t)((brow + ni * 16) * AST + bcol) * 2u;
                ldmx4(bh[ni], bBh + off);
                ldmx4(bl[ni], bBl + off);
            }
            #pragma unroll
            for (int mi = 0; mi < MI; mi++) {
                #pragma unroll
                for (int nj = 0; nj < NJ; nj++) {
                    const uint32_t* ph = &bh[nj >> 1][(nj & 1) * 2];
                    const uint32_t* pl = &bl[nj >> 1][(nj & 1) * 2];
                    mma16816(acc[mi][nj], ah[mi], ph);
                    mma16816(acc[mi][nj], ah[mi], pl);
                    mma16816(acc[mi][nj], al[mi], ph);
                }
            }
        }
        __syncthreads();
    }

    const int r0 = bm0 + wm + (lane >> 2);
    const int c0 = bn0 + wn + (lane & 3) * 2;
    #pragma unroll
    for (int mi = 0; mi < MI; mi++) {
        #pragma unroll
        for (int nj = 0; nj < NJ; nj++) {
            int row = r0 + mi * 16;
            int col = c0 + nj * 8;
            float b0 = bias[col], b1 = bias[col + 1];
            float2 v0 = make_float2(acc[mi][nj][0] + b0, acc[mi][nj][1] + b1);
            float2 v1 = make_float2(acc[mi][nj][2] + b0, acc[mi][nj][3] + b1);
            *reinterpret_cast<float2*>(&C[(size_t)row * N + col]) = v0;
            *reinterpret_cast<float2*>(&C[(size_t)(row + 8) * N + col]) = v1;
        }
    }
}

// smem bytes: 2 buffers x (2*BM + 2*BN) * AST * 2 bytes = (BM+BN)*AST*8
#define GSMEM(BM, BN) ((BM + BN) * AST * 8)

// ---------------------------------------------------------------------------
// chunk_sum: per-chunk (C=64) KV / K sums. grid (NCH, HEADS) = 256 blocks.
// ---------------------------------------------------------------------------
__global__ __launch_bounds__(256)
void chunk_sum_kernel() {
    extern __shared__ float smf[];
    float* rk = smf;                 // [64][64]
    float* vv = rk + CHUNK * DDIM;   // [64][64]
    float* cw = vv + CHUNK * DDIM;   // [64]
    float* sw = cw + CHUNK;          // [64]

    const int c = blockIdx.x, h = blockIdx.y, tid = threadIdx.x;

    for (int t = tid; t < CHUNK * DDIM; t += 256) {
        int i = t >> 6, d = t & 63;
        const float* row = g_qkv + (size_t)(c * CHUNK + i) * E3 + h * DDIM;
        rk[t] = fmaxf(row[EDIM + d], 0.f);
        vv[t] = row[2 * EDIM + d];
    }
    if (tid < CHUNK) {
        float th = (float)(c * CHUNK + tid) * THETA_SCALE;
        cw[tid] = cosf(th);
        sw[tid] = sinf(th);
    }
    __syncthreads();

    const int d  = tid & 63;
    const int eg = (tid >> 6) << 4;
    float aC[16], aS[16];
    #pragma unroll
    for (int e = 0; e < 16; e++) { aC[e] = 0.f; aS[e] = 0.f; }

    for (int i = 0; i < CHUNK; i++) {
        float kd = rk[i * DDIM + d];
        float kc = kd * cw[i];
        float ks = kd * sw[i];
        const float4* vp = reinterpret_cast<const float4*>(&vv[i * DDIM + eg]);
        #pragma unroll
        for (int e4 = 0; e4 < 4; e4++) {
            float4 v4 = vp[e4];
            aC[e4 * 4 + 0] += kc * v4.x; aC[e4 * 4 + 1] += kc * v4.y;
            aC[e4 * 4 + 2] += kc * v4.z; aC[e4 * 4 + 3] += kc * v4.w;
            aS[e4 * 4 + 0] += ks * v4.x; aS[e4 * 4 + 1] += ks * v4.y;
            aS[e4 * 4 + 2] += ks * v4.z; aS[e4 * 4 + 3] += ks * v4.w;
        }
    }

    size_t base = (size_t)(h * NCH + c) * 2 * DDIM * DDIM;
    #pragma unroll
    for (int e = 0; e < 16; e++) {
        g_ckv[base + d * DDIM + eg + e]               = aC[e];
        g_ckv[base + DDIM * DDIM + d * DDIM + eg + e] = aS[e];
    }

    if (tid < DDIM) {
        float sc = 0.f, ss = 0.f;
        for (int i = 0; i < CHUNK; i++) {
            float kd = rk[i * DDIM + tid];
            sc += kd * cw[i];
            ss += kd * sw[i];
        }
        size_t kb = (size_t)(h * NCH + c) * 2 * DDIM;
        g_ck[kb + tid]        = sc;
        g_ck[kb + DDIM + tid] = ss;
    }
}

// ---------------------------------------------------------------------------
// scan: exclusive prefix over 32 chunks. grid 256 x 256, one thread per lane.
// ---------------------------------------------------------------------------
__global__ __launch_bounds__(256)
void scan_kernel() {
    const int h = blockIdx.x >> 5;
    const int idx = (blockIdx.x & 31) * 256 + threadIdx.x;  // 0..8191
    const int KVSZ = 2 * DDIM * DDIM;  // 8192

    float v[NCH];
    #pragma unroll
    for (int c = 0; c < NCH; c++)
        v[c] = g_ckv[(size_t)(h * NCH + c) * KVSZ + idx];
    float run = 0.f;
    #pragma unroll
    for (int c = 0; c < NCH; c++) {
        g_pkv[(size_t)(h * NCH + c) * KVSZ + idx] = run;
        run += v[c];
    }

    if ((blockIdx.x & 31) == 0 && threadIdx.x < 2 * DDIM) {
        const int t = threadIdx.x;
        const int KSZ = 2 * DDIM;
        float w[NCH];
        #pragma unroll
        for (int c = 0; c < NCH; c++)
            w[c] = g_ck[(size_t)(h * NCH + c) * KSZ + t];
        float r2 = 0.f;
        #pragma unroll
        for (int c = 0; c < NCH; c++) {
            g_pk[(size_t)(h * NCH + c) * KSZ + t] = r2;
            r2 += w[c];
        }
    }
}

// ---------------------------------------------------------------------------
// chunk_out (C=64): register-tiled, predicated-causal, fused bf16-split out.
// grid (NCH, HEADS) = 256 blocks, 256 threads.
// ---------------------------------------------------------------------------
#define RQT_STRIDE 68
#define S_STRIDE   66

__global__ __launch_bounds__(256)
void chunk_out_kernel() {
    extern __shared__ float smf[];
    float* rqT = smf;                       // [64][68]
    float* rkT = rqT + DDIM * RQT_STRIDE;   // [64][68]
    float* vv  = rkT + DDIM * RQT_STRIDE;   // [64][64]
    float* S   = vv + CHUNK * DDIM;         // [64][66]
    float* KVc = S + CHUNK * S_STRIDE;      // [64][64]
    float* KVs = KVc + DDIM * DDIM;         // [64][64]
    float* K0c = KVs + DDIM * DDIM;         // [64]
    float* K0s = K0c + DDIM;                // [64]
    float* cw  = K0s + DDIM;                // [64]
    float* sw  = cw + CHUNK;                // [64]
    float* nrm = sw + CHUNK;                // [64]

    const int c = blockIdx.x, h = blockIdx.y, tid = threadIdx.x;

    for (int t = tid; t < CHUNK * DDIM; t += 256) {
        int i = t >> 6, d = t & 63;
        const float* row = g_qkv + (size_t)(c * CHUNK + i) * E3 + h * DDIM;
        rqT[d * RQT_STRIDE + i] = fmaxf(row[d], 0.f);
        rkT[d * RQT_STRIDE + i] = fmaxf(row[EDIM + d], 0.f);
        vv[i * DDIM + d]        = row[2 * EDIM + d];
    }
    if (tid < CHUNK) {
        float th = (float)(c * CHUNK + tid) * THETA_SCALE;
        cw[tid] = cosf(th);
        sw[tid] = sinf(th);
    }
    {
        const float* base = g_pkv + (size_t)(h * NCH + c) * 2 * DDIM * DDIM;
        for (int t = tid; t < 2 * DDIM * DDIM; t += 256) {
            if (t < DDIM * DDIM) KVc[t] = base[t];
            else                 KVs[t - DDIM * DDIM] = base[t];
        }
        const float* kb = g_pk + (size_t)(h * NCH + c) * 2 * DDIM;
        if (tid < 2 * DDIM) {
            if (tid < DDIM) K0c[tid] = kb[tid];
            else            K0s[tid - DDIM] = kb[tid];
        }
    }
    __syncthreads();

    // ---- phase 1: S[i][j] (j<=i), 4x4 tiles on a 16x16 thread grid
    {
        const int ti = tid >> 4, tj = tid & 15;
        const int i0 = ti * 4, j0 = tj * 4;
        if (j0 <= i0 + 3) {
            float acc[4][4];
            #pragma unroll
            for (int r = 0; r < 4; r++)
                #pragma unroll
                for (int q = 0; q < 4; q++) acc[r][q] = 0.f;

            for (int d = 0; d < DDIM; d++) {
                float4 a4 = *reinterpret_cast<const float4*>(&rqT[d * RQT_STRIDE + i0]);
                float4 b4 = *reinterpret_cast<const float4*>(&rkT[d * RQT_STRIDE + j0]);
                float a[4] = {a4.x, a4.y, a4.z, a4.w};
                float b[4] = {b4.x, b4.y, b4.z, b4.w};
                #pragma unroll
                for (int r = 0; r < 4; r++)
                    #pragma unroll
                    for (int q = 0; q < 4; q++)
                        acc[r][q] += a[r] * b[q];
            }
            #pragma unroll
            for (int r = 0; r < 4; r++) {
                int i = i0 + r;
                float ci = cw[i], si = sw[i];
                #pragma unroll
                for (int q = 0; q < 4; q++) {
                    int j = j0 + q;
                    if (j <= i)
                        S[i * S_STRIDE + j] = acc[r][q] * (ci * cw[j] + si * sw[j]);
                }
            }
        }
    }
    __syncthreads();

    // ---- phase 2: nrm
    if (tid < CHUNK) {
        const int i = tid;
        float dc = 0.f, ds = 0.f;
        for (int d = 0; d < DDIM; d++) {
            float q = rqT[d * RQT_STRIDE + i];
            dc += q * K0c[d];
            ds += q * K0s[d];
        }
        float n = cw[i] * dc + sw[i] * ds;
        for (int j = 0; j <= i; j++) n += S[i * S_STRIDE + j];
        nrm[i] = n;
    }
    __syncthreads();

    // ---- phase 3: 2 rows x 8 cols per thread
    const int tx = tid & 7, ty = tid >> 3;
    const int e0 = tx * 8, i0 = ty * 2;

    float tC[2][8], tS[2][8], tI[2][8];
    #pragma unroll
    for (int r = 0; r < 2; r++)
        #pragma unroll
        for (int e = 0; e < 8; e++) { tC[r][e] = 0.f; tS[r][e] = 0.f; tI[r][e] = 0.f; }

    for (int d = 0; d < DDIM; d++) {
        float2 q2 = *reinterpret_cast<const float2*>(&rqT[d * RQT_STRIDE + i0]);
        float qr[2] = {q2.x, q2.y};
        float4 c0 = *reinterpret_cast<const float4*>(&KVc[d * DDIM + e0]);
        float4 c1 = *reinterpret_cast<const float4*>(&KVc[d * DDIM + e0 + 4]);
        float4 s0 = *reinterpret_cast<const float4*>(&KVs[d * DDIM + e0]);
        float4 s1 = *reinterpret_cast<const float4*>(&KVs[d * DDIM + e0 + 4]);
        float cv[8] = {c0.x, c0.y, c0.z, c0.w, c1.x, c1.y, c1.z, c1.w};
        float sv[8] = {s0.x, s0.y, s0.z, s0.w, s1.x, s1.y, s1.z, s1.w};
        #pragma unroll
        for (int r = 0; r < 2; r++)
            #pragma unroll
            for (int e = 0; e < 8; e++) {
                tC[r][e] += qr[r] * cv[e];
                tS[r][e] += qr[r] * sv[e];
            }
    }

    for (int j = 0; j <= i0; j++) {
        float sr[2];
        #pragma unroll
        for (int r = 0; r < 2; r++) sr[r] = S[(i0 + r) * S_STRIDE + j];
        float4 v0 = *reinterpret_cast<const float4*>(&vv[j * DDIM + e0]);
        float4 v1 = *reinterpret_cast<const float4*>(&vv[j * DDIM + e0 + 4]);
        float ve[8] = {v0.x, v0.y, v0.z, v0.w, v1.x, v1.y, v1.z, v1.w};
        #pragma unroll
        for (int r = 0; r < 2; r++)
            #pragma unroll
            for (int e = 0; e < 8; e++)
                tI[r][e] += sr[r] * ve[e];
    }
    {   // tail j = i0+1, valid only for r=1
        const int j = i0 + 1;
        float s1 = S[(i0 + 1) * S_STRIDE + j];
        float4 v0 = *reinterpret_cast<const float4*>(&vv[j * DDIM + e0]);
        float4 v1 = *reinterpret_cast<const float4*>(&vv[j * DDIM + e0 + 4]);
        float ve[8] = {v0.x, v0.y, v0.z, v0.w, v1.x, v1.y, v1.z, v1.w};
        #pragma unroll
        for (int e = 0; e < 8; e++)
            tI[1][e] += s1 * ve[e];
    }

    // ---- epilogue: combine, normalize, bf16 hi/lo split, store
    #pragma unroll
    for (int r = 0; r < 2; r++) {
        const int i = i0 + r;
        float ci = cw[i], si = sw[i];
        float inv = 1.0f / (nrm[i] + 1e-6f);
        uint32_t ph[4], pl[4];
        #pragma unroll
        for (int e2 = 0; e2 < 4; e2++) {
            float v0 = (ci * tC[r][e2 * 2 + 0] + si * tS[r][e2 * 2 + 0] + tI[r][e2 * 2 + 0]) * inv;
            float v1 = (ci * tC[r][e2 * 2 + 1] + si * tS[r][e2 * 2 + 1] + tI[r][e2 * 2 + 1]) * inv;
            __nv_bfloat16 h0 = __float2bfloat16(v0);
            __nv_bfloat16 h1 = __float2bfloat16(v1);
            __nv_bfloat16 l0 = __float2bfloat16(v0 - __bfloat162float(h0));
            __nv_bfloat16 l1 = __float2bfloat16(v1 - __bfloat162float(h1));
            ph[e2] = (uint32_t)__bfloat16_as_ushort(h0) |
                     ((uint32_t)__bfloat16_as_ushort(h1) << 16);
            pl[e2] = (uint32_t)__bfloat16_as_ushort(l0) |
                     ((uint32_t)__bfloat16_as_ushort(l1) << 16);
        }
        size_t base = (size_t)(c * CHUNK + i) * EDIM + h * DDIM + e0;
        *reinterpret_cast<uint4*>(&g_ah[base]) = make_uint4(ph[0], ph[1], ph[2], ph[3]);
        *reinterpret_cast<uint4*>(&g_al[base]) = make_uint4(pl[0], pl[1], pl[2], pl[3]);
    }
}

// ---------------------------------------------------------------------------

static const int SMEM_SUM = (2 * CHUNK * DDIM + 2 * CHUNK) * (int)sizeof(float);
static const int SMEM_OUT = (2 * DDIM * RQT_STRIDE + CHUNK * DDIM + CHUNK * S_STRIDE +
                             2 * DDIM * DDIM + 2 * DDIM + 3 * CHUNK) * (int)sizeof(float);

extern "C" void kernel_launch(void* const* d_in, const int* in_sizes, int n_in,
                              void* d_out, int out_size) {
    (void)in_sizes; (void)n_in; (void)out_size;
    const float* x    = (const float*)d_in[0];
    const float* Wqkv = (const float*)d_in[1];
    const float* bqkv = (const float*)d_in[2];
    const float* Wout = (const float*)d_in[3];
    const float* bout = (const float*)d_in[4];
    float* out = (float*)d_out;

    float* qkv_ptr;
    cudaGetSymbolAddress((void**)&qkv_ptr, g_qkv);
    __nv_bfloat16 *xh, *xl, *wqh, *wql, *woh, *wol, *ah, *al;
    cudaGetSymbolAddress((void**)&xh, g_xh);
    cudaGetSymbolAddress((void**)&xl, g_xl);
    cudaGetSymbolAddress((void**)&wqh, g_wqh);
    cudaGetSymbolAddress((void**)&wql, g_wql);
    cudaGetSymbolAddress((void**)&woh, g_woh);
    cudaGetSymbolAddress((void**)&wol, g_wol);
    cudaGetSymbolAddress((void**)&ah, g_ah);
    cudaGetSymbolAddress((void**)&al, g_al);

    cudaFuncSetAttribute(chunk_sum_kernel,
                         cudaFuncAttributeMaxDynamicSharedMemorySize, SMEM_SUM);
    cudaFuncSetAttribute(chunk_out_kernel,
                         cudaFuncAttributeMaxDynamicSharedMemorySize, SMEM_OUT);
    cudaFuncSetAttribute((const void*)mma_gemm_kernel<128, 128>,
                         cudaFuncAttributeMaxDynamicSharedMemorySize, GSMEM(128, 128));
    cudaFuncSetAttribute((const void*)mma_gemm_kernel<64, 128>,
                         cudaFuncAttributeMaxDynamicSharedMemorySize, GSMEM(64, 128));

    // bf16 splits (inputs)
    split_bf16_kernel<<<(LSEQ * EDIM + 255) / 256, 256>>>(x, xh, xl, LSEQ * EDIM);
    split_bf16_T_kernel<<<dim3(E3 / 32, EDIM / 32), 256>>>(Wqkv, wqh, wql, EDIM, E3);
    split_bf16_T_kernel<<<dim3(EDIM / 32, EDIM / 32), 256>>>(Wout, woh, wol, EDIM, EDIM);

    // 1) QKV GEMM: 128x128 CTA tiles (64x64 warp tiles), grid 192, 2 CTAs/SM
    mma_gemm_kernel<128, 128><<<dim3(E3 / 128, LSEQ / 128), 128, GSMEM(128, 128)>>>(
        xh, xl, wqh, wql, bqkv, qkv_ptr, E3, EDIM);

    // 2) Chunked cosformer attention (C=64, 256-block grids)
    chunk_sum_kernel<<<dim3(NCH, HEADS), 256, SMEM_SUM>>>();
    scan_kernel<<<256, 256>>>();
    chunk_out_kernel<<<dim3(NCH, HEADS), 256, SMEM_OUT>>>();

    // 3) Output GEMM: 64x128 CTA tiles (32x64 warp tiles), grid 128
    mma_gemm_kernel<64, 128><<<dim3(EDIM / 128, LSEQ / 64), 128, GSMEM(64, 128)>>>(
        ah, al, woh, wol, bout, out, EDIM, EDIM);
}

// round 9
// speedup vs baseline: 1.2209x; 1.2209x over previous
#include <cuda_runtime.h>
#include <cuda_bf16.h>
#include <cuda_fp16.h>
#include <cstdint>
#include <cstddef>

// Problem constants
#define LSEQ 2048
#define EDIM 512
#define HEADS 8
#define DDIM 64
#define E3   1536
#define CHUNK 64
#define NCH  32

#define THETA_SCALE 7.66990393942820573e-4f  // (pi/2)/2048

// ---------------- scratch (device globals; no allocs allowed) ----------------
__device__ float g_qkv[LSEQ * E3];
__device__ float g_ckv[HEADS * NCH * 2 * DDIM * DDIM];
__device__ float g_ck [HEADS * NCH * 2 * DDIM];
__device__ float g_pkv[HEADS * NCH * 2 * DDIM * DDIM];
__device__ float g_pk [HEADS * NCH * 2 * DDIM];

// fp16 split buffers (fp16x2 scheme: A = Ah + Al, B = Bh only)
__device__ __half g_xh[LSEQ * EDIM];
__device__ __half g_xl[LSEQ * EDIM];
__device__ __half g_wqh[E3 * EDIM];   // Wqkv^T  [1536][512]
__device__ __half g_woh[EDIM * EDIM]; // Wout^T  [512][512]
__device__ __half g_ah[LSEQ * EDIM];  // attention out hi/lo
__device__ __half g_al[LSEQ * EDIM];

// ---------------- low-level helpers ----------------
__device__ __forceinline__ uint32_t smem_u32(const void* p) {
    uint32_t a;
    asm("{ .reg .u64 t; cvta.to.shared.u64 t, %1; cvt.u32.u64 %0, t; }"
        : "=r"(a) : "l"(p));
    return a;
}
#define CP_ASYNC16(dst, src) \
    asm volatile("cp.async.cg.shared.global [%0], [%1], 16;" :: "r"(dst), "l"(src))
#define CP_COMMIT() asm volatile("cp.async.commit_group;" ::: "memory")
#define CP_WAIT0()  asm volatile("cp.async.wait_group 0;" ::: "memory")
#define CP_WAIT1()  asm volatile("cp.async.wait_group 1;" ::: "memory")

__device__ __forceinline__ void ldmx4(uint32_t* r, uint32_t addr) {
    asm volatile("ldmatrix.sync.aligned.m8n8.x4.shared.b16 {%0,%1,%2,%3}, [%4];"
                 : "=r"(r[0]), "=r"(r[1]), "=r"(r[2]), "=r"(r[3]) : "r"(addr));
}
__device__ __forceinline__ void mma16816(float* c, const uint32_t* a, const uint32_t* b) {
    asm volatile(
        "mma.sync.aligned.m16n8k16.row.col.f32.f16.f16.f32 "
        "{%0,%1,%2,%3}, {%4,%5,%6,%7}, {%8,%9}, {%0,%1,%2,%3};"
        : "+f"(c[0]), "+f"(c[1]), "+f"(c[2]), "+f"(c[3])
        : "r"(a[0]), "r"(a[1]), "r"(a[2]), "r"(a[3]), "r"(b[0]), "r"(b[1]));
}

// ---------------- fp16 split conversion kernels ----------------
__global__ __launch_bounds__(256)
void split_f16_kernel(const float* __restrict__ src,
                      __half* __restrict__ hi, __half* __restrict__ lo, int n) {
    int i = blockIdx.x * 256 + threadIdx.x;
    if (i < n) {
        float a = src[i];
        __half h = __float2half(a);
        hi[i] = h;
        lo[i] = __float2half(a - __half2float(h));
    }
}

// W[K,N] -> WT hi [N,K]  (tiled transpose, hi only — fp16x2 drops B-lo)
__global__ __launch_bounds__(256)
void split_f16_T_kernel(const float* __restrict__ W,
                        __half* __restrict__ hiT, int K, int N) {
    __shared__ float t[32][33];
    const int tx = threadIdx.x & 31, ty = threadIdx.x >> 5;  // (32, 8)
    const int n0 = blockIdx.x * 32, k0 = blockIdx.y * 32;
    #pragma unroll
    for (int j = 0; j < 4; j++)
        t[ty + 8 * j][tx] = W[(size_t)(k0 + ty + 8 * j) * N + n0 + tx];
    __syncthreads();
    #pragma unroll
    for (int j = 0; j < 4; j++) {
        float a = t[tx][ty + 8 * j];  // = W[k0+tx][n0+ty+8j]
        hiT[(size_t)(n0 + ty + 8 * j) * K + k0 + tx] = __float2half(a);
    }
}

// ---------------- mma.sync fp16x2 GEMM: C[M,N] = A @ Bt^T + bias --------------
// A = Ah + Al (fp16 hi/lo), B = Bh (single fp16). 2 MMAs per tile.
// BN = 128 fixed. 8 warps as 2(M) x 4(N): warp tile (BM/2) x 32.
// K-chunk 32, double-buffered cp.async, 3 CTAs/SM (R6-proven geometry).
#define KC 32
#define AST 40   // smem row stride in fp16 elems

template<int BM>
__global__ __launch_bounds__(256, 3)
void mma_gemm_kernel(const __half* __restrict__ Ah, const __half* __restrict__ Al,
                     const __half* __restrict__ Bh,
                     const float* __restrict__ bias, float* __restrict__ C,
                     int N, int K) {
    constexpr int MI = BM / 32;
    constexpr int TILE_A = BM * AST;
    constexpr int TILE_B = 128 * AST;
    constexpr int BUF_E  = 2 * TILE_A + TILE_B;

    extern __shared__ __half smem[];
    const int tid = threadIdx.x;
    const int wid = tid >> 5, lane = tid & 31;
    const int bn0 = blockIdx.x * 128, bm0 = blockIdx.y * BM;
    const int wm = (wid & 1) * (BM / 2);
    const int wn = (wid >> 1) * 32;

    const uint32_t smb = smem_u32(smem);
    const int NCHK = K / KC;

    float acc[MI][4][4];
    #pragma unroll
    for (int mi = 0; mi < MI; mi++)
        #pragma unroll
        for (int nj = 0; nj < 4; nj++)
            #pragma unroll
            for (int r = 0; r < 4; r++) acc[mi][nj][r] = 0.f;

    const __half* srcs[3] = {Ah, Al, Bh};
    const int  srow[3] = {bm0, bm0, bn0};
    const int  titem[3] = {BM * KC / 8, BM * KC / 8, 128 * KC / 8};
    const uint32_t toff[3] = {0u, (uint32_t)TILE_A, (uint32_t)(2 * TILE_A)};

    auto load_chunk = [&](int b, int k0) {
        #pragma unroll
        for (int t = 0; t < 3; t++) {
            const __half* s = srcs[t];
            uint32_t dbase = smb + (uint32_t)(b * BUF_E + toff[t]) * 2u;
            const int nit = titem[t];
            for (int item = tid; item < nit; item += 256) {
                int row = item >> 2, sub = item & 3;
                uint32_t d = dbase + (uint32_t)(row * AST + sub * 8) * 2u;
                const void* g = (const void*)(s + (size_t)(srow[t] + row) * K + k0 + sub * 8);
                CP_ASYNC16(d, g);
            }
        }
        CP_COMMIT();
    };

    load_chunk(0, 0);

    for (int c = 0; c < NCHK; c++) {
        const int b = c & 1;
        if (c + 1 < NCHK) {
            load_chunk(b ^ 1, (c + 1) * KC);
            CP_WAIT1();
        } else {
            CP_WAIT0();
        }
        __syncthreads();

        const uint32_t aBh = smb + (uint32_t)(b * BUF_E) * 2u;
        const uint32_t aBl = aBh + (uint32_t)TILE_A * 2u;
        const uint32_t bBh = aBh + (uint32_t)(2 * TILE_A) * 2u;

        #pragma unroll
        for (int ks = 0; ks < KC; ks += 16) {
            const int arow = wm + (lane & 15);
            const int acol = ks + ((lane >> 4) << 3);
            uint32_t ah[MI][4], al[MI][4];
            #pragma unroll
            for (int mi = 0; mi < MI; mi++) {
                uint32_t off = (uint32_t)((arow + mi * 16) * AST + acol) * 2u;
                ldmx4(ah[mi], aBh + off);
                ldmx4(al[mi], aBl + off);
            }
            const int brow = wn + (lane & 7) + ((lane & 16) ? 8 : 0);
            const int bcol = ks + ((lane & 8) ? 8 : 0);
            uint32_t bh[2][4];
            #pragma unroll
            for (int ni = 0; ni < 2; ni++) {
                uint32_t off = (uint32_t)((brow + ni * 16) * AST + bcol) * 2u;
                ldmx4(bh[ni], bBh + off);
            }
            #pragma unroll
            for (int mi = 0; mi < MI; mi++) {
                #pragma unroll
                for (int nj = 0; nj < 4; nj++) {
                    const uint32_t* ph = &bh[nj >> 1][(nj & 1) * 2];
                    mma16816(acc[mi][nj], ah[mi], ph);
                    mma16816(acc[mi][nj], al[mi], ph);
                }
            }
        }
        __syncthreads();
    }

    const int r0 = bm0 + wm + (lane >> 2);
    const int c0 = bn0 + wn + (lane & 3) * 2;
    #pragma unroll
    for (int mi = 0; mi < MI; mi++) {
        #pragma unroll
        for (int nj = 0; nj < 4; nj++) {
            int row = r0 + mi * 16;
            int col = c0 + nj * 8;
            float b0 = bias[col], b1 = bias[col + 1];
            float2 v0 = make_float2(acc[mi][nj][0] + b0, acc[mi][nj][1] + b1);
            float2 v1 = make_float2(acc[mi][nj][2] + b0, acc[mi][nj][3] + b1);
            *reinterpret_cast<float2*>(&C[(size_t)row * N + col]) = v0;
            *reinterpret_cast<float2*>(&C[(size_t)(row + 8) * N + col]) = v1;
        }
    }
}

// smem bytes: 2 buffers x (2*BM + 128) * AST * 2 bytes
#define GSMEM(BM) ((2 * BM + 128) * AST * 4)

// ---------------------------------------------------------------------------
// chunk_sum: per-chunk (C=64) KV / K sums. grid (NCH, HEADS) = 256 blocks.
// ---------------------------------------------------------------------------
__global__ __launch_bounds__(256)
void chunk_sum_kernel() {
    extern __shared__ float smf[];
    float* rk = smf;                 // [64][64]
    float* vv = rk + CHUNK * DDIM;   // [64][64]
    float* cw = vv + CHUNK * DDIM;   // [64]
    float* sw = cw + CHUNK;          // [64]

    const int c = blockIdx.x, h = blockIdx.y, tid = threadIdx.x;

    for (int t = tid; t < CHUNK * DDIM; t += 256) {
        int i = t >> 6, d = t & 63;
        const float* row = g_qkv + (size_t)(c * CHUNK + i) * E3 + h * DDIM;
        rk[t] = fmaxf(row[EDIM + d], 0.f);
        vv[t] = row[2 * EDIM + d];
    }
    if (tid < CHUNK) {
        float th = (float)(c * CHUNK + tid) * THETA_SCALE;
        cw[tid] = cosf(th);
        sw[tid] = sinf(th);
    }
    __syncthreads();

    const int d  = tid & 63;
    const int eg = (tid >> 6) << 4;
    float aC[16], aS[16];
    #pragma unroll
    for (int e = 0; e < 16; e++) { aC[e] = 0.f; aS[e] = 0.f; }

    for (int i = 0; i < CHUNK; i++) {
        float kd = rk[i * DDIM + d];
        float kc = kd * cw[i];
        float ks = kd * sw[i];
        const float4* vp = reinterpret_cast<const float4*>(&vv[i * DDIM + eg]);
        #pragma unroll
        for (int e4 = 0; e4 < 4; e4++) {
            float4 v4 = vp[e4];
            aC[e4 * 4 + 0] += kc * v4.x; aC[e4 * 4 + 1] += kc * v4.y;
            aC[e4 * 4 + 2] += kc * v4.z; aC[e4 * 4 + 3] += kc * v4.w;
            aS[e4 * 4 + 0] += ks * v4.x; aS[e4 * 4 + 1] += ks * v4.y;
            aS[e4 * 4 + 2] += ks * v4.z; aS[e4 * 4 + 3] += ks * v4.w;
        }
    }

    size_t base = (size_t)(h * NCH + c) * 2 * DDIM * DDIM;
    #pragma unroll
    for (int e = 0; e < 16; e++) {
        g_ckv[base + d * DDIM + eg + e]               = aC[e];
        g_ckv[base + DDIM * DDIM + d * DDIM + eg + e] = aS[e];
    }

    if (tid < DDIM) {
        float sc = 0.f, ss = 0.f;
        for (int i = 0; i < CHUNK; i++) {
            float kd = rk[i * DDIM + tid];
            sc += kd * cw[i];
            ss += kd * sw[i];
        }
        size_t kb = (size_t)(h * NCH + c) * 2 * DDIM;
        g_ck[kb + tid]        = sc;
        g_ck[kb + DDIM + tid] = ss;
    }
}

// ---------------------------------------------------------------------------
// scan: exclusive prefix over 32 chunks. grid 256 x 256, one thread per lane.
// ---------------------------------------------------------------------------
__global__ __launch_bounds__(256)
void scan_kernel() {
    const int h = blockIdx.x >> 5;
    const int idx = (blockIdx.x & 31) * 256 + threadIdx.x;  // 0..8191
    const int KVSZ = 2 * DDIM * DDIM;  // 8192

    float v[NCH];
    #pragma unroll
    for (int c = 0; c < NCH; c++)
        v[c] = g_ckv[(size_t)(h * NCH + c) * KVSZ + idx];
    float run = 0.f;
    #pragma unroll
    for (int c = 0; c < NCH; c++) {
        g_pkv[(size_t)(h * NCH + c) * KVSZ + idx] = run;
        run += v[c];
    }

    if ((blockIdx.x & 31) == 0 && threadIdx.x < 2 * DDIM) {
        const int t = threadIdx.x;
        const int KSZ = 2 * DDIM;
        float w[NCH];
        #pragma unroll
        for (int c = 0; c < NCH; c++)
            w[c] = g_ck[(size_t)(h * NCH + c) * KSZ + t];
        float r2 = 0.f;
        #pragma unroll
        for (int c = 0; c < NCH; c++) {
            g_pk[(size_t)(h * NCH + c) * KSZ + t] = r2;
            r2 += w[c];
        }
    }
}

// ---------------------------------------------------------------------------
// chunk_out (C=64): register-tiled, predicated-causal, fused fp16-split out.
// grid (NCH, HEADS) = 256 blocks, 256 threads.
// ---------------------------------------------------------------------------
#define RQT_STRIDE 68
#define S_STRIDE   66

__global__ __launch_bounds__(256)
void chunk_out_kernel() {
    extern __shared__ float smf[];
    float* rqT = smf;                       // [64][68]
    float* rkT = rqT + DDIM * RQT_STRIDE;   // [64][68]
    float* vv  = rkT + DDIM * RQT_STRIDE;   // [64][64]
    float* S   = vv + CHUNK * DDIM;         // [64][66]
    float* KVc = S + CHUNK * S_STRIDE;      // [64][64]
    float* KVs = KVc + DDIM * DDIM;         // [64][64]
    float* K0c = KVs + DDIM * DDIM;         // [64]
    float* K0s = K0c + DDIM;                // [64]
    float* cw  = K0s + DDIM;                // [64]
    float* sw  = cw + CHUNK;                // [64]
    float* nrm = sw + CHUNK;                // [64]

    const int c = blockIdx.x, h = blockIdx.y, tid = threadIdx.x;

    for (int t = tid; t < CHUNK * DDIM; t += 256) {
        int i = t >> 6, d = t & 63;
        const float* row = g_qkv + (size_t)(c * CHUNK + i) * E3 + h * DDIM;
        rqT[d * RQT_STRIDE + i] = fmaxf(row[d], 0.f);
        rkT[d * RQT_STRIDE + i] = fmaxf(row[EDIM + d], 0.f);
        vv[i * DDIM + d]        = row[2 * EDIM + d];
    }
    if (tid < CHUNK) {
        float th = (float)(c * CHUNK + tid) * THETA_SCALE;
        cw[tid] = cosf(th);
        sw[tid] = sinf(th);
    }
    {
        const float* base = g_pkv + (size_t)(h * NCH + c) * 2 * DDIM * DDIM;
        for (int t = tid; t < 2 * DDIM * DDIM; t += 256) {
            if (t < DDIM * DDIM) KVc[t] = base[t];
            else                 KVs[t - DDIM * DDIM] = base[t];
        }
        const float* kb = g_pk + (size_t)(h * NCH + c) * 2 * DDIM;
        if (tid < 2 * DDIM) {
            if (tid < DDIM) K0c[tid] = kb[tid];
            else            K0s[tid - DDIM] = kb[tid];
        }
    }
    __syncthreads();

    // ---- phase 1: S[i][j] (j<=i), 4x4 tiles on a 16x16 thread grid
    {
        const int ti = tid >> 4, tj = tid & 15;
        const int i0 = ti * 4, j0 = tj * 4;
        if (j0 <= i0 + 3) {
            float acc[4][4];
            #pragma unroll
            for (int r = 0; r < 4; r++)
                #pragma unroll
                for (int q = 0; q < 4; q++) acc[r][q] = 0.f;

            for (int d = 0; d < DDIM; d++) {
                float4 a4 = *reinterpret_cast<const float4*>(&rqT[d * RQT_STRIDE + i0]);
                float4 b4 = *reinterpret_cast<const float4*>(&rkT[d * RQT_STRIDE + j0]);
                float a[4] = {a4.x, a4.y, a4.z, a4.w};
                float b[4] = {b4.x, b4.y, b4.z, b4.w};
                #pragma unroll
                for (int r = 0; r < 4; r++)
                    #pragma unroll
                    for (int q = 0; q < 4; q++)
                        acc[r][q] += a[r] * b[q];
            }
            #pragma unroll
            for (int r = 0; r < 4; r++) {
                int i = i0 + r;
                float ci = cw[i], si = sw[i];
                #pragma unroll
                for (int q = 0; q < 4; q++) {
                    int j = j0 + q;
                    if (j <= i)
                        S[i * S_STRIDE + j] = acc[r][q] * (ci * cw[j] + si * sw[j]);
                }
            }
        }
    }
    __syncthreads();

    // ---- phase 2: nrm
    if (tid < CHUNK) {
        const int i = tid;
        float dc = 0.f, ds = 0.f;
        for (int d = 0; d < DDIM; d++) {
            float q = rqT[d * RQT_STRIDE + i];
            dc += q * K0c[d];
            ds += q * K0s[d];
        }
        float n = cw[i] * dc + sw[i] * ds;
        for (int j = 0; j <= i; j++) n += S[i * S_STRIDE + j];
        nrm[i] = n;
    }
    __syncthreads();

    // ---- phase 3: 2 rows x 8 cols per thread
    const int tx = tid & 7, ty = tid >> 3;
    const int e0 = tx * 8, i0 = ty * 2;

    float tC[2][8], tS[2][8], tI[2][8];
    #pragma unroll
    for (int r = 0; r < 2; r++)
        #pragma unroll
        for (int e = 0; e < 8; e++) { tC[r][e] = 0.f; tS[r][e] = 0.f; tI[r][e] = 0.f; }

    for (int d = 0; d < DDIM; d++) {
        float2 q2 = *reinterpret_cast<const float2*>(&rqT[d * RQT_STRIDE + i0]);
        float qr[2] = {q2.x, q2.y};
        float4 c0 = *reinterpret_cast<const float4*>(&KVc[d * DDIM + e0]);
        float4 c1 = *reinterpret_cast<const float4*>(&KVc[d * DDIM + e0 + 4]);
        float4 s0 = *reinterpret_cast<const float4*>(&KVs[d * DDIM + e0]);
        float4 s1 = *reinterpret_cast<const float4*>(&KVs[d * DDIM + e0 + 4]);
        float cv[8] = {c0.x, c0.y, c0.z, c0.w, c1.x, c1.y, c1.z, c1.w};
        float sv[8] = {s0.x, s0.y, s0.z, s0.w, s1.x, s1.y, s1.z, s1.w};
        #pragma unroll
        for (int r = 0; r < 2; r++)
            #pragma unroll
            for (int e = 0; e < 8; e++) {
                tC[r][e] += qr[r] * cv[e];
                tS[r][e] += qr[r] * sv[e];
            }
    }

    for (int j = 0; j <= i0; j++) {
        float sr[2];
        #pragma unroll
        for (int r = 0; r < 2; r++) sr[r] = S[(i0 + r) * S_STRIDE + j];
        float4 v0 = *reinterpret_cast<const float4*>(&vv[j * DDIM + e0]);
        float4 v1 = *reinterpret_cast<const float4*>(&vv[j * DDIM + e0 + 4]);
        float ve[8] = {v0.x, v0.y, v0.z, v0.w, v1.x, v1.y, v1.z, v1.w};
        #pragma unroll
        for (int r = 0; r < 2; r++)
            #pragma unroll
            for (int e = 0; e < 8; e++)
                tI[r][e] += sr[r] * ve[e];
    }
    {   // tail j = i0+1, valid only for r=1
        const int j = i0 + 1;
        float s1 = S[(i0 + 1) * S_STRIDE + j];
        float4 v0 = *reinterpret_cast<const float4*>(&vv[j * DDIM + e0]);
        float4 v1 = *reinterpret_cast<const float4*>(&vv[j * DDIM + e0 + 4]);
        float ve[8] = {v0.x, v0.y, v0.z, v0.w, v1.x, v1.y, v1.z, v1.w};
        #pragma unroll
        for (int e = 0; e < 8; e++)
            tI[1][e] += s1 * ve[e];
    }

    // ---- epilogue: combine, normalize, fp16 hi/lo split, store
    #pragma unroll
    for (int r = 0; r < 2; r++) {
        const int i = i0 + r;
        float ci = cw[i], si = sw[i];
        float inv = 1.0f / (nrm[i] + 1e-6f);
        uint32_t ph[4], pl[4];
        #pragma unroll
        for (int e2 = 0; e2 < 4; e2++) {
            float v0 = (ci * tC[r][e2 * 2 + 0] + si * tS[r][e2 * 2 + 0] + tI[r][e2 * 2 + 0]) * inv;
            float v1 = (ci * tC[r][e2 * 2 + 1] + si * tS[r][e2 * 2 + 1] + tI[r][e2 * 2 + 1]) * inv;
            __half h0 = __float2half(v0);
            __half h1 = __float2half(v1);
            __half l0 = __float2half(v0 - __half2float(h0));
            __half l1 = __float2half(v1 - __half2float(h1));
            ph[e2] = (uint32_t)__half_as_ushort(h0) |
                     ((uint32_t)__half_as_ushort(h1) << 16);
            pl[e2] = (uint32_t)__half_as_ushort(l0) |
                     ((uint32_t)__half_as_ushort(l1) << 16);
        }
        size_t base = (size_t)(c * CHUNK + i) * EDIM + h * DDIM + e0;
        *reinterpret_cast<uint4*>(&g_ah[base]) = make_uint4(ph[0], ph[1], ph[2], ph[3]);
        *reinterpret_cast<uint4*>(&g_al[base]) = make_uint4(pl[0], pl[1], pl[2], pl[3]);
    }
}

// ---------------------------------------------------------------------------

static const int SMEM_SUM = (2 * CHUNK * DDIM + 2 * CHUNK) * (int)sizeof(float);
static const int SMEM_OUT = (2 * DDIM * RQT_STRIDE + CHUNK * DDIM + CHUNK * S_STRIDE +
                             2 * DDIM * DDIM + 2 * DDIM + 3 * CHUNK) * (int)sizeof(float);

extern "C" void kernel_launch(void* const* d_in, const int* in_sizes, int n_in,
                              void* d_out, int out_size) {
    (void)in_sizes; (void)n_in; (void)out_size;
    const float* x    = (const float*)d_in[0];
    const float* Wqkv = (const float*)d_in[1];
    const float* bqkv = (const float*)d_in[2];
    const float* Wout = (const float*)d_in[3];
    const float* bout = (const float*)d_in[4];
    float* out = (float*)d_out;

    float* qkv_ptr;
    cudaGetSymbolAddress((void**)&qkv_ptr, g_qkv);
    __half *xh, *xl, *wqh, *woh, *ah, *al;
    cudaGetSymbolAddress((void**)&xh, g_xh);
    cudaGetSymbolAddress((void**)&xl, g_xl);
    cudaGetSymbolAddress((void**)&wqh, g_wqh);
    cudaGetSymbolAddress((void**)&woh, g_woh);
    cudaGetSymbolAddress((void**)&ah, g_ah);
    cudaGetSymbolAddress((void**)&al, g_al);

    cudaFuncSetAttribute(chunk_sum_kernel,
                         cudaFuncAttributeMaxDynamicSharedMemorySize, SMEM_SUM);
    cudaFuncSetAttribute(chunk_out_kernel,
                         cudaFuncAttributeMaxDynamicSharedMemorySize, SMEM_OUT);
    cudaFuncSetAttribute((const void*)mma_gemm_kernel<64>,
                         cudaFuncAttributeMaxDynamicSharedMemorySize, GSMEM(64));
    cudaFuncSetAttribute((const void*)mma_gemm_kernel<32>,
                         cudaFuncAttributeMaxDynamicSharedMemorySize, GSMEM(32));

    // fp16 splits (inputs): x -> hi/lo, weights -> hi only (transposed)
    split_f16_kernel<<<(LSEQ * EDIM + 255) / 256, 256>>>(x, xh, xl, LSEQ * EDIM);
    split_f16_T_kernel<<<dim3(E3 / 32, EDIM / 32), 256>>>(Wqkv, wqh, EDIM, E3);
    split_f16_T_kernel<<<dim3(EDIM / 32, EDIM / 32), 256>>>(Wout, woh, EDIM, EDIM);

    // 1) QKV GEMM: 64x128 tiles -> grid 384, 3 CTAs/SM (fp16x2)
    mma_gemm_kernel<64><<<dim3(E3 / 128, LSEQ / 64), 256, GSMEM(64)>>>(
        xh, xl, wqh, bqkv, qkv_ptr, E3, EDIM);

    // 2) Chunked cosformer attention (C=64, 256-block grids)
    chunk_sum_kernel<<<dim3(NCH, HEADS), 256, SMEM_SUM>>>();
    scan_kernel<<<256, 256>>>();
    chunk_out_kernel<<<dim3(NCH, HEADS), 256, SMEM_OUT>>>();

    // 3) Output GEMM: 32x128 tiles -> grid 256 (fp16x2)
    mma_gemm_kernel<32><<<dim3(EDIM / 128, LSEQ / 32), 256, GSMEM(32)>>>(
        ah, al, woh, bout, out, EDIM, EDIM);
}

// round 10
// speedup vs baseline: 1.2508x; 1.0245x over previous
#include <cuda_runtime.h>
#include <cuda_fp16.h>
#include <cstdint>
#include <cstddef>

// Problem constants
#define LSEQ 2048
#define EDIM 512
#define HEADS 8
#define DDIM 64
#define E3   1536
#define CHUNK 64
#define NCH  32

#define THETA_SCALE 7.66990393942820573e-4f  // (pi/2)/2048

// ---------------- scratch (device globals; no allocs allowed) ----------------
__device__ float g_qkv[LSEQ * E3];
__device__ float g_ckv[HEADS * NCH * 2 * DDIM * DDIM];
__device__ float g_ck [HEADS * NCH * 2 * DDIM];
__device__ float g_pkv[HEADS * NCH * 2 * DDIM * DDIM];
__device__ float g_pk [HEADS * NCH * 2 * DDIM];

// fp16 split buffers (fp16x2 scheme: A = Ah + Al, B = Bh only)
__device__ __half g_xh[LSEQ * EDIM];
__device__ __half g_xl[LSEQ * EDIM];
__device__ __half g_wqh[E3 * EDIM];   // Wqkv^T  [1536][512]
__device__ __half g_woh[EDIM * EDIM]; // Wout^T  [512][512]
__device__ __half g_ah[LSEQ * EDIM];  // attention out hi/lo
__device__ __half g_al[LSEQ * EDIM];

// ---------------- low-level helpers ----------------
__device__ __forceinline__ uint32_t smem_u32(const void* p) {
    uint32_t a;
    asm("{ .reg .u64 t; cvta.to.shared.u64 t, %1; cvt.u32.u64 %0, t; }"
        : "=r"(a) : "l"(p));
    return a;
}
#define CP_ASYNC16(dst, src) \
    asm volatile("cp.async.cg.shared.global [%0], [%1], 16;" :: "r"(dst), "l"(src))
#define CP_COMMIT() asm volatile("cp.async.commit_group;" ::: "memory")
#define CP_WAIT0()  asm volatile("cp.async.wait_group 0;" ::: "memory")
#define CP_WAIT1()  asm volatile("cp.async.wait_group 1;" ::: "memory")
#define CP_WAIT2()  asm volatile("cp.async.wait_group 2;" ::: "memory")

__device__ __forceinline__ void ldmx4(uint32_t* r, uint32_t addr) {
    asm volatile("ldmatrix.sync.aligned.m8n8.x4.shared.b16 {%0,%1,%2,%3}, [%4];"
                 : "=r"(r[0]), "=r"(r[1]), "=r"(r[2]), "=r"(r[3]) : "r"(addr));
}
__device__ __forceinline__ void mma16816(float* c, const uint32_t* a, const uint32_t* b) {
    asm volatile(
        "mma.sync.aligned.m16n8k16.row.col.f32.f16.f16.f32 "
        "{%0,%1,%2,%3}, {%4,%5,%6,%7}, {%8,%9}, {%0,%1,%2,%3};"
        : "+f"(c[0]), "+f"(c[1]), "+f"(c[2]), "+f"(c[3])
        : "r"(a[0]), "r"(a[1]), "r"(a[2]), "r"(a[3]), "r"(b[0]), "r"(b[1]));
}

// ---------------- fused split kernel: x hi/lo + both weight transposes ------
__device__ __forceinline__ void transpose_split_tile(
    const float* __restrict__ W, __half* __restrict__ hiT,
    int K, int N, int bx, int by, float (*t)[33]) {
    const int tx = threadIdx.x & 31, ty = threadIdx.x >> 5;  // (32, 8)
    const int n0 = bx * 32, k0 = by * 32;
    #pragma unroll
    for (int j = 0; j < 4; j++)
        t[ty + 8 * j][tx] = W[(size_t)(k0 + ty + 8 * j) * N + n0 + tx];
    __syncthreads();
    #pragma unroll
    for (int j = 0; j < 4; j++)
        hiT[(size_t)(n0 + ty + 8 * j) * K + k0 + tx] = __float2half(t[tx][ty + 8 * j]);
}

__global__ __launch_bounds__(256)
void split_all_kernel(const float* __restrict__ x,
                      const float* __restrict__ Wqkv,
                      const float* __restrict__ Wout) {
    __shared__ float t[32][33];
    const int b = blockIdx.x;
    if (b < 1024) {
        // x split: 1,048,576 elems, 4 per thread, vectorized
        int i = b * 1024 + threadIdx.x * 4;
        float4 a4 = *reinterpret_cast<const float4*>(&x[i]);
        float av[4] = {a4.x, a4.y, a4.z, a4.w};
        __half hv[4], lv[4];
        #pragma unroll
        for (int k = 0; k < 4; k++) {
            hv[k] = __float2half(av[k]);
            lv[k] = __float2half(av[k] - __half2float(hv[k]));
        }
        *reinterpret_cast<uint2*>(&g_xh[i]) = *reinterpret_cast<uint2*>(hv);
        *reinterpret_cast<uint2*>(&g_xl[i]) = *reinterpret_cast<uint2*>(lv);
    } else if (b < 1024 + 768) {
        int tt = b - 1024;                 // Wqkv: K=512, N=1536 -> 48 x 16 tiles
        transpose_split_tile(Wqkv, g_wqh, EDIM, E3, tt % 48, tt / 48, t);
    } else {
        int tt = b - 1024 - 768;           // Wout: K=512, N=512 -> 16 x 16 tiles
        transpose_split_tile(Wout, g_woh, EDIM, EDIM, tt % 16, tt / 16, t);
    }
}

// ---------------- mma.sync fp16x2 GEMM: C[M,N] = A @ Bt^T + bias --------------
// A = Ah + Al (fp16 hi/lo), B = Bh (single fp16). 2 MMAs per tile.
// BN = 128 fixed. 8 warps as 2(M) x 4(N): warp tile (BM/2) x 32.
// K-chunk 32, THREE-stage cp.async pipeline, 3 CTAs/SM.
#define KC 32
#define AST 40   // smem row stride in fp16 elems

template<int BM>
__global__ __launch_bounds__(256, 3)
void mma_gemm_kernel(const __half* __restrict__ Ah, const __half* __restrict__ Al,
                     const __half* __restrict__ Bh,
                     const float* __restrict__ bias, float* __restrict__ C,
                     int N, int K) {
    constexpr int MI = BM / 32;
    constexpr int TILE_A = BM * AST;
    constexpr int TILE_B = 128 * AST;
    constexpr int BUF_E  = 2 * TILE_A + TILE_B;

    extern __shared__ __half smem[];
    const int tid = threadIdx.x;
    const int wid = tid >> 5, lane = tid & 31;
    const int bn0 = blockIdx.x * 128, bm0 = blockIdx.y * BM;
    const int wm = (wid & 1) * (BM / 2);
    const int wn = (wid >> 1) * 32;

    const uint32_t smb = smem_u32(smem);
    const int NCHK = K / KC;

    float acc[MI][4][4];
    #pragma unroll
    for (int mi = 0; mi < MI; mi++)
        #pragma unroll
        for (int nj = 0; nj < 4; nj++)
            #pragma unroll
            for (int r = 0; r < 4; r++) acc[mi][nj][r] = 0.f;

    const __half* srcs[3] = {Ah, Al, Bh};
    const int  srow[3] = {bm0, bm0, bn0};
    const int  titem[3] = {BM * KC / 8, BM * KC / 8, 128 * KC / 8};
    const uint32_t toff[3] = {0u, (uint32_t)TILE_A, (uint32_t)(2 * TILE_A)};

    auto load_chunk = [&](int b, int k0) {
        #pragma unroll
        for (int t = 0; t < 3; t++) {
            const __half* s = srcs[t];
            uint32_t dbase = smb + (uint32_t)(b * BUF_E + toff[t]) * 2u;
            const int nit = titem[t];
            for (int item = tid; item < nit; item += 256) {
                int row = item >> 2, sub = item & 3;
                uint32_t d = dbase + (uint32_t)(row * AST + sub * 8) * 2u;
                const void* g = (const void*)(s + (size_t)(srow[t] + row) * K + k0 + sub * 8);
                CP_ASYNC16(d, g);
            }
        }
        CP_COMMIT();
    };

    load_chunk(0, 0);
    load_chunk(1, KC);

    for (int c = 0; c < NCHK; c++) {
        const int b = c % 3;
        if (c + 2 < NCHK) load_chunk((c + 2) % 3, (c + 2) * KC);
        const int rem = NCHK - 1 - c;
        if (rem >= 2)      CP_WAIT2();
        else if (rem == 1) CP_WAIT1();
        else               CP_WAIT0();
        __syncthreads();

        const uint32_t aBh = smb + (uint32_t)(b * BUF_E) * 2u;
        const uint32_t aBl = aBh + (uint32_t)TILE_A * 2u;
        const uint32_t bBh = aBh + (uint32_t)(2 * TILE_A) * 2u;

        #pragma unroll
        for (int ks = 0; ks < KC; ks += 16) {
            const int arow = wm + (lane & 15);
            const int acol = ks + ((lane >> 4) << 3);
            uint32_t ah[MI][4], al[MI][4];
            #pragma unroll
            for (int mi = 0; mi < MI; mi++) {
                uint32_t off = (uint32_t)((arow + mi * 16) * AST + acol) * 2u;
                ldmx4(ah[mi], aBh + off);
                ldmx4(al[mi], aBl + off);
            }
            const int brow = wn + (lane & 7) + ((lane & 16) ? 8 : 0);
            const int bcol = ks + ((lane & 8) ? 8 : 0);
            uint32_t bh[2][4];
            #pragma unroll
            for (int ni = 0; ni < 2; ni++) {
                uint32_t off = (uint32_t)((brow + ni * 16) * AST + bcol) * 2u;
                ldmx4(bh[ni], bBh + off);
            }
            #pragma unroll
            for (int mi = 0; mi < MI; mi++) {
                #pragma unroll
                for (int nj = 0; nj < 4; nj++) {
                    const uint32_t* ph = &bh[nj >> 1][(nj & 1) * 2];
                    mma16816(acc[mi][nj], ah[mi], ph);
                    mma16816(acc[mi][nj], al[mi], ph);
                }
            }
        }
        __syncthreads();
    }

    const int r0 = bm0 + wm + (lane >> 2);
    const int c0 = bn0 + wn + (lane & 3) * 2;
    #pragma unroll
    for (int mi = 0; mi < MI; mi++) {
        #pragma unroll
        for (int nj = 0; nj < 4; nj++) {
            int row = r0 + mi * 16;
            int col = c0 + nj * 8;
            float b0 = bias[col], b1 = bias[col + 1];
            float2 v0 = make_float2(acc[mi][nj][0] + b0, acc[mi][nj][1] + b1);
            float2 v1 = make_float2(acc[mi][nj][2] + b0, acc[mi][nj][3] + b1);
            *reinterpret_cast<float2*>(&C[(size_t)row * N + col]) = v0;
            *reinterpret_cast<float2*>(&C[(size_t)(row + 8) * N + col]) = v1;
        }
    }
}

// smem bytes: 3 buffers x (2*BM + 128) * AST * 2 bytes
#define GSMEM(BM) ((2 * BM + 128) * AST * 6)

// ---------------------------------------------------------------------------
// chunk_sum: per-chunk (C=64) KV / K sums. grid (NCH, HEADS) = 256 blocks.
// ---------------------------------------------------------------------------
__global__ __launch_bounds__(256)
void chunk_sum_kernel() {
    extern __shared__ float smf[];
    float* rk = smf;                 // [64][64]
    float* vv = rk + CHUNK * DDIM;   // [64][64]
    float* cw = vv + CHUNK * DDIM;   // [64]
    float* sw = cw + CHUNK;          // [64]

    const int c = blockIdx.x, h = blockIdx.y, tid = threadIdx.x;

    for (int t = tid; t < CHUNK * DDIM; t += 256) {
        int i = t >> 6, d = t & 63;
        const float* row = g_qkv + (size_t)(c * CHUNK + i) * E3 + h * DDIM;
        rk[t] = fmaxf(row[EDIM + d], 0.f);
        vv[t] = row[2 * EDIM + d];
    }
    if (tid < CHUNK) {
        float th = (float)(c * CHUNK + tid) * THETA_SCALE;
        cw[tid] = cosf(th);
        sw[tid] = sinf(th);
    }
    __syncthreads();

    const int d  = tid & 63;
    const int eg = (tid >> 6) << 4;
    float aC[16], aS[16];
    #pragma unroll
    for (int e = 0; e < 16; e++) { aC[e] = 0.f; aS[e] = 0.f; }

    for (int i = 0; i < CHUNK; i++) {
        float kd = rk[i * DDIM + d];
        float kc = kd * cw[i];
        float ks = kd * sw[i];
        const float4* vp = reinterpret_cast<const float4*>(&vv[i * DDIM + eg]);
        #pragma unroll
        for (int e4 = 0; e4 < 4; e4++) {
            float4 v4 = vp[e4];
            aC[e4 * 4 + 0] += kc * v4.x; aC[e4 * 4 + 1] += kc * v4.y;
            aC[e4 * 4 + 2] += kc * v4.z; aC[e4 * 4 + 3] += kc * v4.w;
            aS[e4 * 4 + 0] += ks * v4.x; aS[e4 * 4 + 1] += ks * v4.y;
            aS[e4 * 4 + 2] += ks * v4.z; aS[e4 * 4 + 3] += ks * v4.w;
        }
    }

    size_t base = (size_t)(h * NCH + c) * 2 * DDIM * DDIM;
    #pragma unroll
    for (int e = 0; e < 16; e++) {
        g_ckv[base + d * DDIM + eg + e]               = aC[e];
        g_ckv[base + DDIM * DDIM + d * DDIM + eg + e] = aS[e];
    }

    if (tid < DDIM) {
        float sc = 0.f, ss = 0.f;
        for (int i = 0; i < CHUNK; i++) {
            float kd = rk[i * DDIM + tid];
            sc += kd * cw[i];
            ss += kd * sw[i];
        }
        size_t kb = (size_t)(h * NCH + c) * 2 * DDIM;
        g_ck[kb + tid]        = sc;
        g_ck[kb + DDIM + tid] = ss;
    }
}

// ---------------------------------------------------------------------------
// scan: exclusive prefix over 32 chunks. grid 256 x 256, one thread per lane.
// ---------------------------------------------------------------------------
__global__ __launch_bounds__(256)
void scan_kernel() {
    const int h = blockIdx.x >> 5;
    const int idx = (blockIdx.x & 31) * 256 + threadIdx.x;  // 0..8191
    const int KVSZ = 2 * DDIM * DDIM;  // 8192

    float v[NCH];
    #pragma unroll
    for (int c = 0; c < NCH; c++)
        v[c] = g_ckv[(size_t)(h * NCH + c) * KVSZ + idx];
    float run = 0.f;
    #pragma unroll
    for (int c = 0; c < NCH; c++) {
        g_pkv[(size_t)(h * NCH + c) * KVSZ + idx] = run;
        run += v[c];
    }

    if ((blockIdx.x & 31) == 0 && threadIdx.x < 2 * DDIM) {
        const int t = threadIdx.x;
        const int KSZ = 2 * DDIM;
        float w[NCH];
        #pragma unroll
        for (int c = 0; c < NCH; c++)
            w[c] = g_ck[(size_t)(h * NCH + c) * KSZ + t];
        float r2 = 0.f;
        #pragma unroll
        for (int c = 0; c < NCH; c++) {
            g_pk[(size_t)(h * NCH + c) * KSZ + t] = r2;
            r2 += w[c];
        }
    }
}

// ---------------------------------------------------------------------------
// chunk_out (C=64): register-tiled, predicated-causal, fused fp16-split out.
// grid (NCH, HEADS) = 256 blocks, 256 threads.
// ---------------------------------------------------------------------------
#define RQT_STRIDE 68
#define S_STRIDE   66

__global__ __launch_bounds__(256)
void chunk_out_kernel() {
    extern __shared__ float smf[];
    float* rqT = smf;                       // [64][68]
    float* rkT = rqT + DDIM * RQT_STRIDE;   // [64][68]
    float* vv  = rkT + DDIM * RQT_STRIDE;   // [64][64]
    float* S   = vv + CHUNK * DDIM;         // [64][66]
    float* KVc = S + CHUNK * S_STRIDE;      // [64][64]
    float* KVs = KVc + DDIM * DDIM;         // [64][64]
    float* K0c = KVs + DDIM * DDIM;         // [64]
    float* K0s = K0c + DDIM;                // [64]
    float* cw  = K0s + DDIM;                // [64]
    float* sw  = cw + CHUNK;                // [64]
    float* nrm = sw + CHUNK;                // [64]

    const int c = blockIdx.x, h = blockIdx.y, tid = threadIdx.x;

    for (int t = tid; t < CHUNK * DDIM; t += 256) {
        int i = t >> 6, d = t & 63;
        const float* row = g_qkv + (size_t)(c * CHUNK + i) * E3 + h * DDIM;
        rqT[d * RQT_STRIDE + i] = fmaxf(row[d], 0.f);
        rkT[d * RQT_STRIDE + i] = fmaxf(row[EDIM + d], 0.f);
        vv[i * DDIM + d]        = row[2 * EDIM + d];
    }
    if (tid < CHUNK) {
        float th = (float)(c * CHUNK + tid) * THETA_SCALE;
        cw[tid] = cosf(th);
        sw[tid] = sinf(th);
    }
    {
        const float* base = g_pkv + (size_t)(h * NCH + c) * 2 * DDIM * DDIM;
        for (int t = tid; t < 2 * DDIM * DDIM; t += 256) {
            if (t < DDIM * DDIM) KVc[t] = base[t];
            else                 KVs[t - DDIM * DDIM] = base[t];
        }
        const float* kb = g_pk + (size_t)(h * NCH + c) * 2 * DDIM;
        if (tid < 2 * DDIM) {
            if (tid < DDIM) K0c[tid] = kb[tid];
            else            K0s[tid - DDIM] = kb[tid];
        }
    }
    __syncthreads();

    // ---- phase 1: S[i][j] (j<=i), 4x4 tiles on a 16x16 thread grid
    {
        const int ti = tid >> 4, tj = tid & 15;
        const int i0 = ti * 4, j0 = tj * 4;
        if (j0 <= i0 + 3) {
            float acc[4][4];
            #pragma unroll
            for (int r = 0; r < 4; r++)
                #pragma unroll
                for (int q = 0; q < 4; q++) acc[r][q] = 0.f;

            for (int d = 0; d < DDIM; d++) {
                float4 a4 = *reinterpret_cast<const float4*>(&rqT[d * RQT_STRIDE + i0]);
                float4 b4 = *reinterpret_cast<const float4*>(&rkT[d * RQT_STRIDE + j0]);
                float a[4] = {a4.x, a4.y, a4.z, a4.w};
                float b[4] = {b4.x, b4.y, b4.z, b4.w};
                #pragma unroll
                for (int r = 0; r < 4; r++)
                    #pragma unroll
                    for (int q = 0; q < 4; q++)
                        acc[r][q] += a[r] * b[q];
            }
            #pragma unroll
            for (int r = 0; r < 4; r++) {
                int i = i0 + r;
                float ci = cw[i], si = sw[i];
                #pragma unroll
                for (int q = 0; q < 4; q++) {
                    int j = j0 + q;
                    if (j <= i)
                        S[i * S_STRIDE + j] = acc[r][q] * (ci * cw[j] + si * sw[j]);
                }
            }
        }
    }
    __syncthreads();

    // ---- phase 2: nrm
    if (tid < CHUNK) {
        const int i = tid;
        float dc = 0.f, ds = 0.f;
        for (int d = 0; d < DDIM; d++) {
            float q = rqT[d * RQT_STRIDE + i];
            dc += q * K0c[d];
            ds += q * K0s[d];
        }
        float n = cw[i] * dc + sw[i] * ds;
        for (int j = 0; j <= i; j++) n += S[i * S_STRIDE + j];
        nrm[i] = n;
    }
    __syncthreads();

    // ---- phase 3: 2 rows x 8 cols per thread
    const int tx = tid & 7, ty = tid >> 3;
    const int e0 = tx * 8, i0 = ty * 2;

    float tC[2][8], tS[2][8], tI[2][8];
    #pragma unroll
    for (int r = 0; r < 2; r++)
        #pragma unroll
        for (int e = 0; e < 8; e++) { tC[r][e] = 0.f; tS[r][e] = 0.f; tI[r][e] = 0.f; }

    for (int d = 0; d < DDIM; d++) {
        float2 q2 = *reinterpret_cast<const float2*>(&rqT[d * RQT_STRIDE + i0]);
        float qr[2] = {q2.x, q2.y};
        float4 c0 = *reinterpret_cast<const float4*>(&KVc[d * DDIM + e0]);
        float4 c1 = *reinterpret_cast<const float4*>(&KVc[d * DDIM + e0 + 4]);
        float4 s0 = *reinterpret_cast<const float4*>(&KVs[d * DDIM + e0]);
        float4 s1 = *reinterpret_cast<const float4*>(&KVs[d * DDIM + e0 + 4]);
        float cv[8] = {c0.x, c0.y, c0.z, c0.w, c1.x, c1.y, c1.z, c1.w};
        float sv[8] = {s0.x, s0.y, s0.z, s0.w, s1.x, s1.y, s1.z, s1.w};
        #pragma unroll
        for (int r = 0; r < 2; r++)
            #pragma unroll
            for (int e = 0; e < 8; e++) {
                tC[r][e] += qr[r] * cv[e];
                tS[r][e] += qr[r] * sv[e];
            }
    }

    for (int j = 0; j <= i0; j++) {
        float sr[2];
        #pragma unroll
        for (int r = 0; r < 2; r++) sr[r] = S[(i0 + r) * S_STRIDE + j];
        float4 v0 = *reinterpret_cast<const float4*>(&vv[j * DDIM + e0]);
        float4 v1 = *reinterpret_cast<const float4*>(&vv[j * DDIM + e0 + 4]);
        float ve[8] = {v0.x, v0.y, v0.z, v0.w, v1.x, v1.y, v1.z, v1.w};
        #pragma unroll
        for (int r = 0; r < 2; r++)
            #pragma unroll
            for (int e = 0; e < 8; e++)
                tI[r][e] += sr[r] * ve[e];
    }
    {   // tail j = i0+1, valid only for r=1
        const int j = i0 + 1;
        float s1 = S[(i0 + 1) * S_STRIDE + j];
        float4 v0 = *reinterpret_cast<const float4*>(&vv[j * DDIM + e0]);
        float4 v1 = *reinterpret_cast<const float4*>(&vv[j * DDIM + e0 + 4]);
        float ve[8] = {v0.x, v0.y, v0.z, v0.w, v1.x, v1.y, v1.z, v1.w};
        #pragma unroll
        for (int e = 0; e < 8; e++)
            tI[1][e] += s1 * ve[e];
    }

    // ---- epilogue: combine, normalize, fp16 hi/lo split, store
    #pragma unroll
    for (int r = 0; r < 2; r++) {
        const int i = i0 + r;
        float ci = cw[i], si = sw[i];
        float inv = 1.0f / (nrm[i] + 1e-6f);
        uint32_t ph[4], pl[4];
        #pragma unroll
        for (int e2 = 0; e2 < 4; e2++) {
            float v0 = (ci * tC[r][e2 * 2 + 0] + si * tS[r][e2 * 2 + 0] + tI[r][e2 * 2 + 0]) * inv;
            float v1 = (ci * tC[r][e2 * 2 + 1] + si * tS[r][e2 * 2 + 1] + tI[r][e2 * 2 + 1]) * inv;
            __half h0 = __float2half(v0);
            __half h1 = __float2half(v1);
            __half l0 = __float2half(v0 - __half2float(h0));
            __half l1 = __float2half(v1 - __half2float(h1));
            ph[e2] = (uint32_t)__half_as_ushort(h0) |
                     ((uint32_t)__half_as_ushort(h1) << 16);
            pl[e2] = (uint32_t)__half_as_ushort(l0) |
                     ((uint32_t)__half_as_ushort(l1) << 16);
        }
        size_t base = (size_t)(c * CHUNK + i) * EDIM + h * DDIM + e0;
        *reinterpret_cast<uint4*>(&g_ah[base]) = make_uint4(ph[0], ph[1], ph[2], ph[3]);
        *reinterpret_cast<uint4*>(&g_al[base]) = make_uint4(pl[0], pl[1], pl[2], pl[3]);
    }
}

// ---------------------------------------------------------------------------

static const int SMEM_SUM = (2 * CHUNK * DDIM + 2 * CHUNK) * (int)sizeof(float);
static const int SMEM_OUT = (2 * DDIM * RQT_STRIDE + CHUNK * DDIM + CHUNK * S_STRIDE +
                             2 * DDIM * DDIM + 2 * DDIM + 3 * CHUNK) * (int)sizeof(float);

extern "C" void kernel_launch(void* const* d_in, const int* in_sizes, int n_in,
                              void* d_out, int out_size) {
    (void)in_sizes; (void)n_in; (void)out_size;
    const float* x    = (const float*)d_in[0];
    const float* Wqkv = (const float*)d_in[1];
    const float* bqkv = (const float*)d_in[2];
    const float* Wout = (const float*)d_in[3];
    const float* bout = (const float*)d_in[4];
    float* out = (float*)d_out;

    float* qkv_ptr;
    cudaGetSymbolAddress((void**)&qkv_ptr, g_qkv);
    __half *xh, *xl, *wqh, *woh, *ah, *al;
    cudaGetSymbolAddress((void**)&xh, g_xh);
    cudaGetSymbolAddress((void**)&xl, g_xl);
    cudaGetSymbolAddress((void**)&wqh, g_wqh);
    cudaGetSymbolAddress((void**)&woh, g_woh);
    cudaGetSymbolAddress((void**)&ah, g_ah);
    cudaGetSymbolAddress((void**)&al, g_al);

    cudaFuncSetAttribute(chunk_sum_kernel,
                         cudaFuncAttributeMaxDynamicSharedMemorySize, SMEM_SUM);
    cudaFuncSetAttribute(chunk_out_kernel,
                         cudaFuncAttributeMaxDynamicSharedMemorySize, SMEM_OUT);
    cudaFuncSetAttribute((const void*)mma_gemm_kernel<64>,
                         cudaFuncAttributeMaxDynamicSharedMemorySize, GSMEM(64));
    cudaFuncSetAttribute((const void*)mma_gemm_kernel<32>,
                         cudaFuncAttributeMaxDynamicSharedMemorySize, GSMEM(32));

    // fused fp16 splits: x hi/lo + Wqkv^T hi + Wout^T hi, one launch
    split_all_kernel<<<1024 + 768 + 256, 256>>>(x, Wqkv, Wout);

    // 1) QKV GEMM: 64x128 tiles -> grid 384, 3 CTAs/SM, 3-stage pipeline
    mma_gemm_kernel<64><<<dim3(E3 / 128, LSEQ / 64), 256, GSMEM(64)>>>(
        xh, xl, wqh, bqkv, qkv_ptr, E3, EDIM);

    // 2) Chunked cosformer attention (C=64, 256-block grids)
    chunk_sum_kernel<<<dim3(NCH, HEADS), 256, SMEM_SUM>>>();
    scan_kernel<<<256, 256>>>();
    chunk_out_kernel<<<dim3(NCH, HEADS), 256, SMEM_OUT>>>();

    // 3) Output GEMM: 32x128 tiles -> grid 256, 3-stage pipeline
    mma_gemm_kernel<32><<<dim3(EDIM / 128, LSEQ / 32), 256, GSMEM(32)>>>(
        ah, al, woh, bout, out, EDIM, EDIM);
}